// round 3
// baseline (speedup 1.0000x reference)
#include <cuda_runtime.h>
#include <math.h>

#define D_      3072
#define H_      24
#define HD_     128
#define R_      32
#define INNER_  3072
#define QKV3_   9216
#define SIMG_   1536
#define STXT_   512
#define SALL_   2048

// ---------------- scratch (device globals; no runtime allocation) ----------
static __device__ float g_qkv_img[SIMG_ * QKV3_];
static __device__ float g_qkv_txt[STXT_ * QKV3_];
static __device__ float g_lr_a[SIMG_ * R_];
static __device__ float g_lr_b[STXT_ * R_];
static __device__ float g_q[H_ * SALL_ * HD_];
static __device__ float g_k[H_ * SALL_ * HD_];
static __device__ float g_v[H_ * SALL_ * HD_];
static __device__ float g_attn[SALL_ * INNER_];

// ---------------------------------------------------------------------------
// C[M,N] = A[M,K] @ B[N,K]^T (+ bias[n]).  M,N multiples of 128, K of 16.
// 256 threads, 128x128 tile, 8x8 microtile.
// ---------------------------------------------------------------------------
__global__ void __launch_bounds__(256) gemm_nt_kernel(
    const float* __restrict__ A, const float* __restrict__ B,
    const float* __restrict__ bias, float* __restrict__ C,
    int M, int N, int K)
{
    __shared__ float As[16][128];
    __shared__ float Bs[16][128];

    const int tid = threadIdx.x;
    const int tx = tid & 15;
    const int ty = tid >> 4;
    const int brow = blockIdx.y * 128;
    const int bcol = blockIdx.x * 128;
    const int lr = tid >> 2;          // 0..63
    const int lk = (tid & 3) * 4;     // 0,4,8,12

    const float* Arow0 = A + (size_t)(brow + lr) * K + lk;
    const float* Arow1 = A + (size_t)(brow + lr + 64) * K + lk;
    const float* Brow0 = B + (size_t)(bcol + lr) * K + lk;
    const float* Brow1 = B + (size_t)(bcol + lr + 64) * K + lk;

    float acc[8][8];
#pragma unroll
    for (int i = 0; i < 8; i++)
#pragma unroll
        for (int j = 0; j < 8; j++) acc[i][j] = 0.f;

    for (int kt = 0; kt < K; kt += 16) {
        float4 a0 = *(const float4*)(Arow0 + kt);
        float4 a1 = *(const float4*)(Arow1 + kt);
        float4 b0 = *(const float4*)(Brow0 + kt);
        float4 b1 = *(const float4*)(Brow1 + kt);
        __syncthreads();
        As[lk + 0][lr] = a0.x; As[lk + 1][lr] = a0.y;
        As[lk + 2][lr] = a0.z; As[lk + 3][lr] = a0.w;
        As[lk + 0][lr + 64] = a1.x; As[lk + 1][lr + 64] = a1.y;
        As[lk + 2][lr + 64] = a1.z; As[lk + 3][lr + 64] = a1.w;
        Bs[lk + 0][lr] = b0.x; Bs[lk + 1][lr] = b0.y;
        Bs[lk + 2][lr] = b0.z; Bs[lk + 3][lr] = b0.w;
        Bs[lk + 0][lr + 64] = b1.x; Bs[lk + 1][lr + 64] = b1.y;
        Bs[lk + 2][lr + 64] = b1.z; Bs[lk + 3][lr + 64] = b1.w;
        __syncthreads();
#pragma unroll
        for (int k = 0; k < 16; k++) {
            float a[8], b[8];
            *(float4*)&a[0] = *(const float4*)&As[k][ty * 4];
            *(float4*)&a[4] = *(const float4*)&As[k][64 + ty * 4];
            *(float4*)&b[0] = *(const float4*)&Bs[k][tx * 4];
            *(float4*)&b[4] = *(const float4*)&Bs[k][64 + tx * 4];
#pragma unroll
            for (int i = 0; i < 8; i++)
#pragma unroll
                for (int j = 0; j < 8; j++)
                    acc[i][j] += a[i] * b[j];
        }
    }

#pragma unroll
    for (int ih = 0; ih < 2; ih++)
#pragma unroll
        for (int ii = 0; ii < 4; ii++) {
            int r = brow + ih * 64 + ty * 4 + ii;
            float* crow = C + (size_t)r * N + bcol;
#pragma unroll
            for (int jh = 0; jh < 2; jh++) {
                int c0 = jh * 64 + tx * 4;
                float4 v;
                v.x = acc[ih * 4 + ii][jh * 4 + 0];
                v.y = acc[ih * 4 + ii][jh * 4 + 1];
                v.z = acc[ih * 4 + ii][jh * 4 + 2];
                v.w = acc[ih * 4 + ii][jh * 4 + 3];
                if (bias) {
                    v.x += bias[bcol + c0 + 0];
                    v.y += bias[bcol + c0 + 1];
                    v.z += bias[bcol + c0 + 2];
                    v.w += bias[bcol + c0 + 3];
                }
                *(float4*)(crow + c0) = v;
            }
        }
}

// ---------------------------------------------------------------------------
// C[M,R] = A[M,K] @ B[K,R] ; R = 32, K multiple of 8.  One block per row.
// ---------------------------------------------------------------------------
__global__ void __launch_bounds__(256) down_proj_kernel(
    const float* __restrict__ A, const float* __restrict__ B,
    float* __restrict__ C, int K)
{
    const int m = blockIdx.x;
    const int c = threadIdx.x & 31;
    const int kc = threadIdx.x >> 5;  // 0..7
    const float* a = A + (size_t)m * K;
    const int kchunk = K >> 3;
    const int k0 = kc * kchunk;
    float s = 0.f;
    for (int k = k0; k < k0 + kchunk; k++)
        s += a[k] * B[k * R_ + c];
    __shared__ float red[256];
    red[threadIdx.x] = s;
    __syncthreads();
    if (kc == 0) {
        float t = s;
#pragma unroll
        for (int i = 1; i < 8; i++) t += red[i * 32 + c];
        C[m * R_ + c] = t;
    }
}

// ---------------------------------------------------------------------------
// C[M,N] += T[M,32] @ U[32,N]  (N multiple of 4)
// ---------------------------------------------------------------------------
__global__ void __launch_bounds__(256) rank_update_kernel(
    const float* __restrict__ T, const float* __restrict__ U,
    float* __restrict__ C, int M, int N)
{
    const int n4cnt = N >> 2;
    long long idx = (long long)blockIdx.x * blockDim.x + threadIdx.x;
    if (idx >= (long long)M * n4cnt) return;
    int m = (int)(idx / n4cnt);
    int n4 = (int)(idx % n4cnt);
    float4 c = ((float4*)C)[(size_t)m * n4cnt + n4];
    const float* t = T + (size_t)m * R_;
#pragma unroll
    for (int k = 0; k < R_; k++) {
        float tv = t[k];
        float4 u = ((const float4*)(U + (size_t)k * N))[n4];
        c.x += tv * u.x; c.y += tv * u.y; c.z += tv * u.z; c.w += tv * u.w;
    }
    ((float4*)C)[(size_t)m * n4cnt + n4] = c;
}

// ---------------------------------------------------------------------------
// QKV post-process: split heads, RMSNorm q/k, RoPE, scatter to [H][S][HD].
// grid (S, H), 128 threads.
// ---------------------------------------------------------------------------
__global__ void __launch_bounds__(128) qkv_post_kernel(
    const float* __restrict__ qkv, int pos_off,
    const float* __restrict__ wq, const float* __restrict__ wk,
    const float* __restrict__ rcos, const float* __restrict__ rsin,
    float* __restrict__ gq, float* __restrict__ gk, float* __restrict__ gv)
{
    const int s = blockIdx.x;
    const int h = blockIdx.y;
    const int d = threadIdx.x;
    const float* row = qkv + (size_t)s * QKV3_ + h * HD_;
    float q = row[d];
    float k = row[INNER_ + d];
    float v = row[2 * INNER_ + d];

    __shared__ float sh[8];
    float sq = q * q, sk = k * k;
#pragma unroll
    for (int o = 16; o > 0; o >>= 1) {
        sq += __shfl_xor_sync(0xffffffffu, sq, o);
        sk += __shfl_xor_sync(0xffffffffu, sk, o);
    }
    int w = d >> 5;
    if ((d & 31) == 0) { sh[w] = sq; sh[4 + w] = sk; }
    __syncthreads();
    sq = sh[0] + sh[1] + sh[2] + sh[3];
    sk = sh[4] + sh[5] + sh[6] + sh[7];
    float rq = rsqrtf(sq * (1.f / HD_) + 1e-5f);
    float rk = rsqrtf(sk * (1.f / HD_) + 1e-5f);
    q = q * rq * wq[d];
    k = k * rk * wk[d];

    const int pos = pos_off + s;
    float c = rcos[pos * 64 + (d >> 1)];
    float sn = rsin[pos * 64 + (d >> 1)];
    float qo = __shfl_xor_sync(0xffffffffu, q, 1);
    float ko = __shfl_xor_sync(0xffffffffu, k, 1);
    float qr = (d & 1) ? (qo * sn + q * c) : (q * c - qo * sn);
    float kr = (d & 1) ? (ko * sn + k * c) : (k * c - ko * sn);

    size_t o = ((size_t)h * SALL_ + pos) * HD_ + d;
    gq[o] = qr; gk[o] = kr; gv[o] = v;
}

// ---------------------------------------------------------------------------
// Flash attention: grid (SALL/64, H), 256 threads, dynamic smem.
// BM=64 queries, BKV=32 keys/tile.  Thread (ty,tx): ty=rows group (4 rows),
// tx = cols (score phase: k = tx, tx+16) / dims (PV phase: d = tx*8..tx*8+7)
// ---------------------------------------------------------------------------
#define KS_ 132
#define PS_ 33
#define ATTN_SMEM_BYTES ((64*128 + 32*KS_ + 32*128 + 64*PS_) * 4)

__global__ void __launch_bounds__(256) attn_kernel(
    const float* __restrict__ Q, const float* __restrict__ Kg,
    const float* __restrict__ Vg, float* __restrict__ O)
{
    extern __shared__ float sm[];
    float* Qs = sm;                    // 64*128
    float* Ks = Qs + 64 * 128;         // 32*KS_
    float* Vs = Ks + 32 * KS_;         // 32*128
    float* Ps = Vs + 32 * 128;         // 64*PS_

    const int head = blockIdx.y;
    const int q0 = blockIdx.x * 64;
    const int tid = threadIdx.x;
    const int tx = tid & 15;
    const int ty = tid >> 4;
    const float scale = 0.08838834764831845f;  // 1/sqrt(128)

    const float* Qh = Q + ((size_t)head * SALL_ + q0) * HD_;
    const float* Kh = Kg + (size_t)head * SALL_ * HD_;
    const float* Vh = Vg + (size_t)head * SALL_ * HD_;

    for (int i = tid; i < 64 * 128 / 4; i += 256) {
        float4 v = ((const float4*)Qh)[i];
        v.x *= scale; v.y *= scale; v.z *= scale; v.w *= scale;
        ((float4*)Qs)[i] = v;
    }

    float m[4], l[4], acc[4][8];
#pragma unroll
    for (int i = 0; i < 4; i++) {
        m[i] = -1e30f; l[i] = 0.f;
#pragma unroll
        for (int e = 0; e < 8; e++) acc[i][e] = 0.f;
    }

    for (int kt = 0; kt < SALL_; kt += 32) {
        __syncthreads();
        const float* kp = Kh + (size_t)kt * HD_;
        const float* vp = Vh + (size_t)kt * HD_;
        for (int i = tid; i < 32 * 128 / 4; i += 256) {
            int r = i >> 5, c = i & 31;
            float4 kv = ((const float4*)kp)[i];
            *(float4*)&Ks[r * KS_ + c * 4] = kv;
            float4 vv = ((const float4*)vp)[i];
            *(float4*)&Vs[r * 128 + c * 4] = vv;
        }
        __syncthreads();

        // ---- scores: s[i][j], cols c = tx (j=0), tx+16 (j=1)
        float s[4][2];
#pragma unroll
        for (int i = 0; i < 4; i++) { s[i][0] = 0.f; s[i][1] = 0.f; }
#pragma unroll 8
        for (int d4 = 0; d4 < 32; d4++) {
            float4 k0 = *(const float4*)&Ks[tx * KS_ + d4 * 4];
            float4 k1 = *(const float4*)&Ks[(tx + 16) * KS_ + d4 * 4];
#pragma unroll
            for (int i = 0; i < 4; i++) {
                float4 q = *(const float4*)&Qs[(ty * 4 + i) * 128 + d4 * 4];
                s[i][0] += q.x * k0.x + q.y * k0.y + q.z * k0.z + q.w * k0.w;
                s[i][1] += q.x * k1.x + q.y * k1.y + q.z * k1.z + q.w * k1.w;
            }
        }

        float resc[4];
#pragma unroll
        for (int i = 0; i < 4; i++) {
            float mloc = fmaxf(s[i][0], s[i][1]);
#pragma unroll
            for (int o = 8; o > 0; o >>= 1)
                mloc = fmaxf(mloc, __shfl_xor_sync(0xffffffffu, mloc, o));
            float mnew = fmaxf(m[i], mloc);
            float sc = __expf(m[i] - mnew);
            float p0 = __expf(s[i][0] - mnew);
            float p1 = __expf(s[i][1] - mnew);
            float ls = p0 + p1;
#pragma unroll
            for (int o = 8; o > 0; o >>= 1)
                ls += __shfl_xor_sync(0xffffffffu, ls, o);
            l[i] = l[i] * sc + ls;
            m[i] = mnew;
            resc[i] = sc;
            Ps[(ty * 4 + i) * PS_ + tx] = p0;
            Ps[(ty * 4 + i) * PS_ + tx + 16] = p1;
        }
        __syncthreads();

        // ---- PV: acc[i][e], dims d = tx*8 + e
#pragma unroll
        for (int i = 0; i < 4; i++)
#pragma unroll
            for (int e = 0; e < 8; e++) acc[i][e] *= resc[i];
#pragma unroll 8
        for (int k = 0; k < 32; k++) {
            float4 v0 = *(const float4*)&Vs[k * 128 + tx * 8];
            float4 v1 = *(const float4*)&Vs[k * 128 + tx * 8 + 4];
#pragma unroll
            for (int i = 0; i < 4; i++) {
                float p = Ps[(ty * 4 + i) * PS_ + k];
                acc[i][0] += p * v0.x; acc[i][1] += p * v0.y;
                acc[i][2] += p * v0.z; acc[i][3] += p * v0.w;
                acc[i][4] += p * v1.x; acc[i][5] += p * v1.y;
                acc[i][6] += p * v1.z; acc[i][7] += p * v1.w;
            }
        }
    }

#pragma unroll
    for (int i = 0; i < 4; i++) {
        float inv = 1.f / l[i];
        int q = q0 + ty * 4 + i;
        float* orow = O + (size_t)q * INNER_ + head * HD_ + tx * 8;
        float4 v0, v1;
        v0.x = acc[i][0] * inv; v0.y = acc[i][1] * inv;
        v0.z = acc[i][2] * inv; v0.w = acc[i][3] * inv;
        v1.x = acc[i][4] * inv; v1.y = acc[i][5] * inv;
        v1.z = acc[i][6] * inv; v1.w = acc[i][7] * inv;
        *(float4*)orow = v0;
        *(float4*)(orow + 4) = v1;
    }
}

// ---------------------------------------------------------------------------
extern "C" void kernel_launch(void* const* d_in, const int* in_sizes, int n_in,
                              void* d_out, int out_size)
{
    const float* hs        = (const float*)d_in[0];
    const float* ehs       = (const float*)d_in[1];
    const float* rcos      = (const float*)d_in[2];
    const float* rsin      = (const float*)d_in[3];
    const float* qkv_w     = (const float*)d_in[4];
    const float* qkv_down  = (const float*)d_in[5];
    const float* qkv_up    = (const float*)d_in[6];
    const float* aqkv_w    = (const float*)d_in[7];
    const float* aqkv_down = (const float*)d_in[8];
    const float* aqkv_up   = (const float*)d_in[9];
    const float* out_w     = (const float*)d_in[10];
    const float* out_down  = (const float*)d_in[11];
    const float* out_up    = (const float*)d_in[12];
    const float* out_b     = (const float*)d_in[13];
    const float* aout_w    = (const float*)d_in[14];
    const float* aout_down = (const float*)d_in[15];
    const float* aout_up   = (const float*)d_in[16];
    const float* aout_b    = (const float*)d_in[17];
    const float* nq        = (const float*)d_in[18];
    const float* nk        = (const float*)d_in[19];
    const float* naq       = (const float*)d_in[20];
    const float* nak       = (const float*)d_in[21];

    float *qkv_img, *qkv_txt, *lr_a, *lr_b, *Q, *K, *V, *attn;
    cudaGetSymbolAddress((void**)&qkv_img, g_qkv_img);
    cudaGetSymbolAddress((void**)&qkv_txt, g_qkv_txt);
    cudaGetSymbolAddress((void**)&lr_a, g_lr_a);
    cudaGetSymbolAddress((void**)&lr_b, g_lr_b);
    cudaGetSymbolAddress((void**)&Q, g_q);
    cudaGetSymbolAddress((void**)&K, g_k);
    cudaGetSymbolAddress((void**)&V, g_v);
    cudaGetSymbolAddress((void**)&attn, g_attn);

    float* out_img = (float*)d_out;                      // (1536,3072)
    float* out_txt = (float*)d_out + (size_t)SIMG_ * D_; // (512,3072)

    // ---- QKV projections (dense + low-rank) ----
    down_proj_kernel<<<SIMG_, 256>>>(hs, qkv_down, lr_a, D_);
    gemm_nt_kernel<<<dim3(QKV3_ / 128, SIMG_ / 128), 256>>>(
        hs, qkv_w, nullptr, qkv_img, SIMG_, QKV3_, D_);
    {
        long long tot = (long long)SIMG_ * (QKV3_ / 4);
        rank_update_kernel<<<(unsigned)((tot + 255) / 256), 256>>>(
            lr_a, qkv_up, qkv_img, SIMG_, QKV3_);
    }
    down_proj_kernel<<<STXT_, 256>>>(ehs, aqkv_down, lr_b, D_);
    gemm_nt_kernel<<<dim3(QKV3_ / 128, STXT_ / 128), 256>>>(
        ehs, aqkv_w, nullptr, qkv_txt, STXT_, QKV3_, D_);
    {
        long long tot = (long long)STXT_ * (QKV3_ / 4);
        rank_update_kernel<<<(unsigned)((tot + 255) / 256), 256>>>(
            lr_b, aqkv_up, qkv_txt, STXT_, QKV3_);
    }

    // ---- heads + RMSNorm + RoPE; concat order: txt (pos 0..511), img (512..) ----
    qkv_post_kernel<<<dim3(STXT_, H_), 128>>>(qkv_txt, 0, naq, nak, rcos, rsin, Q, K, V);
    qkv_post_kernel<<<dim3(SIMG_, H_), 128>>>(qkv_img, STXT_, nq, nk, rcos, rsin, Q, K, V);

    // ---- attention ----
    cudaFuncSetAttribute(attn_kernel, cudaFuncAttributeMaxDynamicSharedMemorySize,
                         ATTN_SMEM_BYTES);
    attn_kernel<<<dim3(SALL_ / 64, H_), 256, ATTN_SMEM_BYTES>>>(Q, K, V, attn);

    // ---- output projections ----
    const float* attn_txt = attn;
    const float* attn_img = attn + (size_t)STXT_ * INNER_;

    down_proj_kernel<<<SIMG_, 256>>>(attn_img, out_down, lr_a, INNER_);
    gemm_nt_kernel<<<dim3(D_ / 128, SIMG_ / 128), 256>>>(
        attn_img, out_w, out_b, out_img, SIMG_, D_, INNER_);
    {
        long long tot = (long long)SIMG_ * (D_ / 4);
        rank_update_kernel<<<(unsigned)((tot + 255) / 256), 256>>>(
            lr_a, out_up, out_img, SIMG_, D_);
    }
    down_proj_kernel<<<STXT_, 256>>>(attn_txt, aout_down, lr_b, INNER_);
    gemm_nt_kernel<<<dim3(D_ / 128, STXT_ / 128), 256>>>(
        attn_txt, aout_w, aout_b, out_txt, STXT_, D_, INNER_);
    {
        long long tot = (long long)STXT_ * (D_ / 4);
        rank_update_kernel<<<(unsigned)((tot + 255) / 256), 256>>>(
            lr_b, aout_up, out_txt, STXT_, D_);
    }
}

// round 4
// speedup vs baseline: 1.5817x; 1.5817x over previous
#include <cuda_runtime.h>
#include <cuda_bf16.h>
#include <math.h>
#include <stdint.h>

#define D_      3072
#define H_      24
#define HD_     128
#define R_      32
#define INNER_  3072
#define QKV3_   9216
#define SIMG_   1536
#define STXT_   512
#define SALL_   2048

// ---------------- scratch (device globals; no runtime allocation) ----------
static __device__ float g_qkv_img[SIMG_ * QKV3_];
static __device__ float g_qkv_txt[STXT_ * QKV3_];
static __device__ float g_lr_a[SIMG_ * R_];
static __device__ float g_lr_b[STXT_ * R_];
static __device__ float g_q[H_ * SALL_ * HD_];
static __device__ float g_k[H_ * SALL_ * HD_];
static __device__ float g_v[H_ * SALL_ * HD_];
static __device__ float g_attn[SALL_ * INNER_];

// bf16 hi/lo split buffers
static __device__ __nv_bfloat16 g_Aih[SIMG_ * D_],  g_Ail[SIMG_ * D_];   // img A
static __device__ __nv_bfloat16 g_Ath[STXT_ * D_],  g_Atl[STXT_ * D_];   // txt A
static __device__ __nv_bfloat16 g_Bqh[QKV3_ * D_],  g_Bql[QKV3_ * D_];   // qkv_w
static __device__ __nv_bfloat16 g_Baqh[QKV3_ * D_], g_Baql[QKV3_ * D_];  // add_qkv_w
static __device__ __nv_bfloat16 g_Boh[D_ * INNER_], g_Bol[D_ * INNER_];  // out_w
static __device__ __nv_bfloat16 g_Baoh[D_ * INNER_], g_Baol[D_ * INNER_];// add_out_w

// ---------------------------------------------------------------------------
// fp32 -> bf16 hi/lo split (elementwise), n multiple of 4
// ---------------------------------------------------------------------------
__global__ void __launch_bounds__(256) split_bf16_kernel(
    const float* __restrict__ X, __nv_bfloat16* __restrict__ Xh,
    __nv_bfloat16* __restrict__ Xl, int n4)
{
    int i = blockIdx.x * blockDim.x + threadIdx.x;
    if (i >= n4) return;
    float4 v = ((const float4*)X)[i];
    union { __nv_bfloat16 b[4]; uint2 u; } ph, pl;
    ph.b[0] = __float2bfloat16(v.x);
    ph.b[1] = __float2bfloat16(v.y);
    ph.b[2] = __float2bfloat16(v.z);
    ph.b[3] = __float2bfloat16(v.w);
    pl.b[0] = __float2bfloat16(v.x - __bfloat162float(ph.b[0]));
    pl.b[1] = __float2bfloat16(v.y - __bfloat162float(ph.b[1]));
    pl.b[2] = __float2bfloat16(v.z - __bfloat162float(ph.b[2]));
    pl.b[3] = __float2bfloat16(v.w - __bfloat162float(ph.b[3]));
    ((uint2*)Xh)[i] = ph.u;
    ((uint2*)Xl)[i] = pl.u;
}

// ---------------------------------------------------------------------------
// mma helpers
// ---------------------------------------------------------------------------
__device__ __forceinline__ uint32_t sptr(const void* p) {
    return (uint32_t)__cvta_generic_to_shared(p);
}
__device__ __forceinline__ void ldsm_x4(uint32_t* r, uint32_t a) {
    asm volatile("ldmatrix.sync.aligned.m8n8.x4.shared.b16 {%0,%1,%2,%3}, [%4];"
                 : "=r"(r[0]), "=r"(r[1]), "=r"(r[2]), "=r"(r[3]) : "r"(a));
}
__device__ __forceinline__ void mma_bf16(float* c, const uint32_t* a,
                                         uint32_t b0, uint32_t b1) {
    asm volatile(
        "mma.sync.aligned.m16n8k16.row.col.f32.bf16.bf16.f32 "
        "{%0,%1,%2,%3},{%4,%5,%6,%7},{%8,%9},{%0,%1,%2,%3};"
        : "+f"(c[0]), "+f"(c[1]), "+f"(c[2]), "+f"(c[3])
        : "r"(a[0]), "r"(a[1]), "r"(a[2]), "r"(a[3]), "r"(b0), "r"(b1));
}

// ---------------------------------------------------------------------------
// C[M,N] = A[M,K] @ B[N,K]^T (+bias), A,B given as bf16 hi/lo pairs.
// Computes Ah*Bh + Ah*Bl + Al*Bh with fp32 accumulate (≈ fp32 accuracy).
// 128x128 tile, k-tile 32, 256 threads (8 warps as 2M x 4N, warp tile 64x32).
// ---------------------------------------------------------------------------
#define LDA_ 40   // smem halves per row (32 data + 8 pad) -> conflict-free ldmatrix

__global__ void __launch_bounds__(256) gemm_mma_kernel(
    const __nv_bfloat16* __restrict__ Ah, const __nv_bfloat16* __restrict__ Al,
    const __nv_bfloat16* __restrict__ Bh, const __nv_bfloat16* __restrict__ Bl,
    const float* __restrict__ bias, float* __restrict__ C,
    int M, int N, int K)
{
    __shared__ __nv_bfloat16 sAh[128 * LDA_], sAl[128 * LDA_];
    __shared__ __nv_bfloat16 sBh[128 * LDA_], sBl[128 * LDA_];

    const int tid  = threadIdx.x;
    const int brow = blockIdx.y * 128;
    const int bcol = blockIdx.x * 128;
    const int warp = tid >> 5, lane = tid & 31;
    const int wm = (warp & 1) * 64;
    const int wn = (warp >> 1) * 32;

    // global load mapping: 2 x uint4 per array per thread per k-tile
    const int lrow = tid >> 2;          // 0..63 (and +64)
    const int lseg = (tid & 3) * 8;     // half offset 0,8,16,24
    const __nv_bfloat16* pAh0 = Ah + (size_t)(brow + lrow) * K + lseg;
    const __nv_bfloat16* pAh1 = Ah + (size_t)(brow + lrow + 64) * K + lseg;
    const __nv_bfloat16* pAl0 = Al + (size_t)(brow + lrow) * K + lseg;
    const __nv_bfloat16* pAl1 = Al + (size_t)(brow + lrow + 64) * K + lseg;
    const __nv_bfloat16* pBh0 = Bh + (size_t)(bcol + lrow) * K + lseg;
    const __nv_bfloat16* pBh1 = Bh + (size_t)(bcol + lrow + 64) * K + lseg;
    const __nv_bfloat16* pBl0 = Bl + (size_t)(bcol + lrow) * K + lseg;
    const __nv_bfloat16* pBl1 = Bl + (size_t)(bcol + lrow + 64) * K + lseg;

    float acc[4][4][4];
#pragma unroll
    for (int i = 0; i < 4; i++)
#pragma unroll
        for (int j = 0; j < 4; j++)
#pragma unroll
            for (int e = 0; e < 4; e++) acc[i][j][e] = 0.f;

    // ldmatrix lane addressing (constant over loop)
    const int qa = lane >> 3, ra = lane & 7;
    const int a_row = (qa & 1) * 8 + ra;     // + mf*16 + wm
    const int a_col = (qa >> 1) * 8;         // + kb
    const int b_row = (qa >> 1) * 8 + ra;    // + p*16 + wn
    const int b_col = (qa & 1) * 8;          // + kb

    for (int kt = 0; kt < K; kt += 32) {
        uint4 vah0 = *(const uint4*)(pAh0 + kt);
        uint4 vah1 = *(const uint4*)(pAh1 + kt);
        uint4 val0 = *(const uint4*)(pAl0 + kt);
        uint4 val1 = *(const uint4*)(pAl1 + kt);
        uint4 vbh0 = *(const uint4*)(pBh0 + kt);
        uint4 vbh1 = *(const uint4*)(pBh1 + kt);
        uint4 vbl0 = *(const uint4*)(pBl0 + kt);
        uint4 vbl1 = *(const uint4*)(pBl1 + kt);
        __syncthreads();
        *(uint4*)&sAh[lrow * LDA_ + lseg]        = vah0;
        *(uint4*)&sAh[(lrow + 64) * LDA_ + lseg] = vah1;
        *(uint4*)&sAl[lrow * LDA_ + lseg]        = val0;
        *(uint4*)&sAl[(lrow + 64) * LDA_ + lseg] = val1;
        *(uint4*)&sBh[lrow * LDA_ + lseg]        = vbh0;
        *(uint4*)&sBh[(lrow + 64) * LDA_ + lseg] = vbh1;
        *(uint4*)&sBl[lrow * LDA_ + lseg]        = vbl0;
        *(uint4*)&sBl[(lrow + 64) * LDA_ + lseg] = vbl1;
        __syncthreads();

#pragma unroll
        for (int kb = 0; kb < 32; kb += 16) {
            uint32_t ah[4][4], al[4][4], bh[2][4], bl[2][4];
#pragma unroll
            for (int mf = 0; mf < 4; mf++) {
                int r = wm + mf * 16 + a_row;
                ldsm_x4(ah[mf], sptr(&sAh[r * LDA_ + kb + a_col]));
                ldsm_x4(al[mf], sptr(&sAl[r * LDA_ + kb + a_col]));
            }
#pragma unroll
            for (int p = 0; p < 2; p++) {
                int r = wn + p * 16 + b_row;
                ldsm_x4(bh[p], sptr(&sBh[r * LDA_ + kb + b_col]));
                ldsm_x4(bl[p], sptr(&sBl[r * LDA_ + kb + b_col]));
            }
#pragma unroll
            for (int mf = 0; mf < 4; mf++)
#pragma unroll
                for (int nf = 0; nf < 4; nf++) {
                    const int p = nf >> 1, o = (nf & 1) * 2;
                    mma_bf16(acc[mf][nf], ah[mf], bh[p][o], bh[p][o + 1]);
                    mma_bf16(acc[mf][nf], ah[mf], bl[p][o], bl[p][o + 1]);
                    mma_bf16(acc[mf][nf], al[mf], bh[p][o], bh[p][o + 1]);
                }
        }
    }

    // epilogue: lane (g=lane/4, t=lane%4): rows g, g+8; cols 2t, 2t+1
    const int g = lane >> 2, t = lane & 3;
#pragma unroll
    for (int mf = 0; mf < 4; mf++) {
        int r0 = brow + wm + mf * 16 + g;
#pragma unroll
        for (int nf = 0; nf < 4; nf++) {
            int col = bcol + wn + nf * 8 + t * 2;
            float b0 = 0.f, b1 = 0.f;
            if (bias) { b0 = bias[col]; b1 = bias[col + 1]; }
            float2 v0, v1;
            v0.x = acc[mf][nf][0] + b0; v0.y = acc[mf][nf][1] + b1;
            v1.x = acc[mf][nf][2] + b0; v1.y = acc[mf][nf][3] + b1;
            *(float2*)(C + (size_t)r0 * N + col)       = v0;
            *(float2*)(C + (size_t)(r0 + 8) * N + col) = v1;
        }
    }
}

// ---------------------------------------------------------------------------
// C[M,R] = A[M,K] @ B[K,R] ; R = 32.  One block per row.
// ---------------------------------------------------------------------------
__global__ void __launch_bounds__(256) down_proj_kernel(
    const float* __restrict__ A, const float* __restrict__ B,
    float* __restrict__ C, int K)
{
    const int m = blockIdx.x;
    const int c = threadIdx.x & 31;
    const int kc = threadIdx.x >> 5;
    const float* a = A + (size_t)m * K;
    const int kchunk = K >> 3;
    const int k0 = kc * kchunk;
    float s = 0.f;
    for (int k = k0; k < k0 + kchunk; k++)
        s += a[k] * B[k * R_ + c];
    __shared__ float red[256];
    red[threadIdx.x] = s;
    __syncthreads();
    if (kc == 0) {
        float t = s;
#pragma unroll
        for (int i = 1; i < 8; i++) t += red[i * 32 + c];
        C[m * R_ + c] = t;
    }
}

// ---------------------------------------------------------------------------
// C[M,N] += T[M,32] @ U[32,N]
// ---------------------------------------------------------------------------
__global__ void __launch_bounds__(256) rank_update_kernel(
    const float* __restrict__ T, const float* __restrict__ U,
    float* __restrict__ C, int M, int N)
{
    const int n4cnt = N >> 2;
    long long idx = (long long)blockIdx.x * blockDim.x + threadIdx.x;
    if (idx >= (long long)M * n4cnt) return;
    int m = (int)(idx / n4cnt);
    int n4 = (int)(idx % n4cnt);
    float4 c = ((float4*)C)[(size_t)m * n4cnt + n4];
    const float* t = T + (size_t)m * R_;
#pragma unroll
    for (int k = 0; k < R_; k++) {
        float tv = t[k];
        float4 u = ((const float4*)(U + (size_t)k * N))[n4];
        c.x += tv * u.x; c.y += tv * u.y; c.z += tv * u.z; c.w += tv * u.w;
    }
    ((float4*)C)[(size_t)m * n4cnt + n4] = c;
}

// ---------------------------------------------------------------------------
// QKV post-process: split heads, RMSNorm q/k, RoPE, scatter to [H][S][HD].
// ---------------------------------------------------------------------------
__global__ void __launch_bounds__(128) qkv_post_kernel(
    const float* __restrict__ qkv, int pos_off,
    const float* __restrict__ wq, const float* __restrict__ wk,
    const float* __restrict__ rcos, const float* __restrict__ rsin,
    float* __restrict__ gq, float* __restrict__ gk, float* __restrict__ gv)
{
    const int s = blockIdx.x;
    const int h = blockIdx.y;
    const int d = threadIdx.x;
    const float* row = qkv + (size_t)s * QKV3_ + h * HD_;
    float q = row[d];
    float k = row[INNER_ + d];
    float v = row[2 * INNER_ + d];

    __shared__ float sh[8];
    float sq = q * q, sk = k * k;
#pragma unroll
    for (int o = 16; o > 0; o >>= 1) {
        sq += __shfl_xor_sync(0xffffffffu, sq, o);
        sk += __shfl_xor_sync(0xffffffffu, sk, o);
    }
    int w = d >> 5;
    if ((d & 31) == 0) { sh[w] = sq; sh[4 + w] = sk; }
    __syncthreads();
    sq = sh[0] + sh[1] + sh[2] + sh[3];
    sk = sh[4] + sh[5] + sh[6] + sh[7];
    float rq = rsqrtf(sq * (1.f / HD_) + 1e-5f);
    float rk = rsqrtf(sk * (1.f / HD_) + 1e-5f);
    q = q * rq * wq[d];
    k = k * rk * wk[d];

    const int pos = pos_off + s;
    float c = rcos[pos * 64 + (d >> 1)];
    float sn = rsin[pos * 64 + (d >> 1)];
    float qo = __shfl_xor_sync(0xffffffffu, q, 1);
    float ko = __shfl_xor_sync(0xffffffffu, k, 1);
    float qr = (d & 1) ? (qo * sn + q * c) : (q * c - qo * sn);
    float kr = (d & 1) ? (ko * sn + k * c) : (k * c - ko * sn);

    size_t o = ((size_t)h * SALL_ + pos) * HD_ + d;
    gq[o] = qr; gk[o] = kr; gv[o] = v;
}

// ---------------------------------------------------------------------------
// Flash attention: grid (SALL/64, H), 256 threads, dynamic smem.
// ---------------------------------------------------------------------------
#define KS_ 132
#define PS_ 33
#define ATTN_SMEM_BYTES ((64*128 + 32*KS_ + 32*128 + 64*PS_) * 4)

__global__ void __launch_bounds__(256) attn_kernel(
    const float* __restrict__ Q, const float* __restrict__ Kg,
    const float* __restrict__ Vg, float* __restrict__ O)
{
    extern __shared__ float sm[];
    float* Qs = sm;
    float* Ks = Qs + 64 * 128;
    float* Vs = Ks + 32 * KS_;
    float* Ps = Vs + 32 * 128;

    const int head = blockIdx.y;
    const int q0 = blockIdx.x * 64;
    const int tid = threadIdx.x;
    const int tx = tid & 15;
    const int ty = tid >> 4;
    const float scale = 0.08838834764831845f;

    const float* Qh = Q + ((size_t)head * SALL_ + q0) * HD_;
    const float* Kh = Kg + (size_t)head * SALL_ * HD_;
    const float* Vh = Vg + (size_t)head * SALL_ * HD_;

    for (int i = tid; i < 64 * 128 / 4; i += 256) {
        float4 v = ((const float4*)Qh)[i];
        v.x *= scale; v.y *= scale; v.z *= scale; v.w *= scale;
        ((float4*)Qs)[i] = v;
    }

    float m[4], l[4], acc[4][8];
#pragma unroll
    for (int i = 0; i < 4; i++) {
        m[i] = -1e30f; l[i] = 0.f;
#pragma unroll
        for (int e = 0; e < 8; e++) acc[i][e] = 0.f;
    }

    for (int kt = 0; kt < SALL_; kt += 32) {
        __syncthreads();
        const float* kp = Kh + (size_t)kt * HD_;
        const float* vp = Vh + (size_t)kt * HD_;
        for (int i = tid; i < 32 * 128 / 4; i += 256) {
            int r = i >> 5, c = i & 31;
            float4 kv = ((const float4*)kp)[i];
            *(float4*)&Ks[r * KS_ + c * 4] = kv;
            float4 vv = ((const float4*)vp)[i];
            *(float4*)&Vs[r * 128 + c * 4] = vv;
        }
        __syncthreads();

        float s[4][2];
#pragma unroll
        for (int i = 0; i < 4; i++) { s[i][0] = 0.f; s[i][1] = 0.f; }
#pragma unroll 8
        for (int d4 = 0; d4 < 32; d4++) {
            float4 k0 = *(const float4*)&Ks[tx * KS_ + d4 * 4];
            float4 k1 = *(const float4*)&Ks[(tx + 16) * KS_ + d4 * 4];
#pragma unroll
            for (int i = 0; i < 4; i++) {
                float4 q = *(const float4*)&Qs[(ty * 4 + i) * 128 + d4 * 4];
                s[i][0] += q.x * k0.x + q.y * k0.y + q.z * k0.z + q.w * k0.w;
                s[i][1] += q.x * k1.x + q.y * k1.y + q.z * k1.z + q.w * k1.w;
            }
        }

        float resc[4];
#pragma unroll
        for (int i = 0; i < 4; i++) {
            float mloc = fmaxf(s[i][0], s[i][1]);
#pragma unroll
            for (int o = 8; o > 0; o >>= 1)
                mloc = fmaxf(mloc, __shfl_xor_sync(0xffffffffu, mloc, o));
            float mnew = fmaxf(m[i], mloc);
            float sc = __expf(m[i] - mnew);
            float p0 = __expf(s[i][0] - mnew);
            float p1 = __expf(s[i][1] - mnew);
            float ls = p0 + p1;
#pragma unroll
            for (int o = 8; o > 0; o >>= 1)
                ls += __shfl_xor_sync(0xffffffffu, ls, o);
            l[i] = l[i] * sc + ls;
            m[i] = mnew;
            resc[i] = sc;
            Ps[(ty * 4 + i) * PS_ + tx] = p0;
            Ps[(ty * 4 + i) * PS_ + tx + 16] = p1;
        }
        __syncthreads();

#pragma unroll
        for (int i = 0; i < 4; i++)
#pragma unroll
            for (int e = 0; e < 8; e++) acc[i][e] *= resc[i];
#pragma unroll 8
        for (int k = 0; k < 32; k++) {
            float4 v0 = *(const float4*)&Vs[k * 128 + tx * 8];
            float4 v1 = *(const float4*)&Vs[k * 128 + tx * 8 + 4];
#pragma unroll
            for (int i = 0; i < 4; i++) {
                float p = Ps[(ty * 4 + i) * PS_ + k];
                acc[i][0] += p * v0.x; acc[i][1] += p * v0.y;
                acc[i][2] += p * v0.z; acc[i][3] += p * v0.w;
                acc[i][4] += p * v1.x; acc[i][5] += p * v1.y;
                acc[i][6] += p * v1.z; acc[i][7] += p * v1.w;
            }
        }
    }

#pragma unroll
    for (int i = 0; i < 4; i++) {
        float inv = 1.f / l[i];
        int q = q0 + ty * 4 + i;
        float* orow = O + (size_t)q * INNER_ + head * HD_ + tx * 8;
        float4 v0, v1;
        v0.x = acc[i][0] * inv; v0.y = acc[i][1] * inv;
        v0.z = acc[i][2] * inv; v0.w = acc[i][3] * inv;
        v1.x = acc[i][4] * inv; v1.y = acc[i][5] * inv;
        v1.z = acc[i][6] * inv; v1.w = acc[i][7] * inv;
        *(float4*)orow = v0;
        *(float4*)(orow + 4) = v1;
    }
}

// ---------------------------------------------------------------------------
static inline void split_launch(const float* X, __nv_bfloat16* h, __nv_bfloat16* l,
                                long long n)
{
    int n4 = (int)(n >> 2);
    split_bf16_kernel<<<(n4 + 255) / 256, 256>>>(X, h, l, n4);
}

extern "C" void kernel_launch(void* const* d_in, const int* in_sizes, int n_in,
                              void* d_out, int out_size)
{
    const float* hs        = (const float*)d_in[0];
    const float* ehs       = (const float*)d_in[1];
    const float* rcos      = (const float*)d_in[2];
    const float* rsin      = (const float*)d_in[3];
    const float* qkv_w     = (const float*)d_in[4];
    const float* qkv_down  = (const float*)d_in[5];
    const float* qkv_up    = (const float*)d_in[6];
    const float* aqkv_w    = (const float*)d_in[7];
    const float* aqkv_down = (const float*)d_in[8];
    const float* aqkv_up   = (const float*)d_in[9];
    const float* out_w     = (const float*)d_in[10];
    const float* out_down  = (const float*)d_in[11];
    const float* out_up    = (const float*)d_in[12];
    const float* out_b     = (const float*)d_in[13];
    const float* aout_w    = (const float*)d_in[14];
    const float* aout_down = (const float*)d_in[15];
    const float* aout_up   = (const float*)d_in[16];
    const float* aout_b    = (const float*)d_in[17];
    const float* nq        = (const float*)d_in[18];
    const float* nk        = (const float*)d_in[19];
    const float* naq       = (const float*)d_in[20];
    const float* nak       = (const float*)d_in[21];

    float *qkv_img, *qkv_txt, *lr_a, *lr_b, *Q, *K, *V, *attn;
    cudaGetSymbolAddress((void**)&qkv_img, g_qkv_img);
    cudaGetSymbolAddress((void**)&qkv_txt, g_qkv_txt);
    cudaGetSymbolAddress((void**)&lr_a, g_lr_a);
    cudaGetSymbolAddress((void**)&lr_b, g_lr_b);
    cudaGetSymbolAddress((void**)&Q, g_q);
    cudaGetSymbolAddress((void**)&K, g_k);
    cudaGetSymbolAddress((void**)&V, g_v);
    cudaGetSymbolAddress((void**)&attn, g_attn);

    __nv_bfloat16 *Aih, *Ail, *Ath, *Atl;
    __nv_bfloat16 *Bqh, *Bql, *Baqh, *Baql, *Boh, *Bol, *Baoh, *Baol;
    cudaGetSymbolAddress((void**)&Aih, g_Aih);
    cudaGetSymbolAddress((void**)&Ail, g_Ail);
    cudaGetSymbolAddress((void**)&Ath, g_Ath);
    cudaGetSymbolAddress((void**)&Atl, g_Atl);
    cudaGetSymbolAddress((void**)&Bqh, g_Bqh);
    cudaGetSymbolAddress((void**)&Bql, g_Bql);
    cudaGetSymbolAddress((void**)&Baqh, g_Baqh);
    cudaGetSymbolAddress((void**)&Baql, g_Baql);
    cudaGetSymbolAddress((void**)&Boh, g_Boh);
    cudaGetSymbolAddress((void**)&Bol, g_Bol);
    cudaGetSymbolAddress((void**)&Baoh, g_Baoh);
    cudaGetSymbolAddress((void**)&Baol, g_Baol);

    float* out_img = (float*)d_out;
    float* out_txt = (float*)d_out + (size_t)SIMG_ * D_;

    // ---- bf16 hi/lo conversions ----
    split_launch(hs,     Aih,  Ail,  (long long)SIMG_ * D_);
    split_launch(ehs,    Ath,  Atl,  (long long)STXT_ * D_);
    split_launch(qkv_w,  Bqh,  Bql,  (long long)QKV3_ * D_);
    split_launch(aqkv_w, Baqh, Baql, (long long)QKV3_ * D_);
    split_launch(out_w,  Boh,  Bol,  (long long)D_ * INNER_);
    split_launch(aout_w, Baoh, Baol, (long long)D_ * INNER_);

    // ---- QKV projections (tensor-core dense + fp32 low-rank) ----
    down_proj_kernel<<<SIMG_, 256>>>(hs, qkv_down, lr_a, D_);
    gemm_mma_kernel<<<dim3(QKV3_ / 128, SIMG_ / 128), 256>>>(
        Aih, Ail, Bqh, Bql, nullptr, qkv_img, SIMG_, QKV3_, D_);
    {
        long long tot = (long long)SIMG_ * (QKV3_ / 4);
        rank_update_kernel<<<(unsigned)((tot + 255) / 256), 256>>>(
            lr_a, qkv_up, qkv_img, SIMG_, QKV3_);
    }
    down_proj_kernel<<<STXT_, 256>>>(ehs, aqkv_down, lr_b, D_);
    gemm_mma_kernel<<<dim3(QKV3_ / 128, STXT_ / 128), 256>>>(
        Ath, Atl, Baqh, Baql, nullptr, qkv_txt, STXT_, QKV3_, D_);
    {
        long long tot = (long long)STXT_ * (QKV3_ / 4);
        rank_update_kernel<<<(unsigned)((tot + 255) / 256), 256>>>(
            lr_b, aqkv_up, qkv_txt, STXT_, QKV3_);
    }

    // ---- heads + RMSNorm + RoPE (txt first, then img) ----
    qkv_post_kernel<<<dim3(STXT_, H_), 128>>>(qkv_txt, 0, naq, nak, rcos, rsin, Q, K, V);
    qkv_post_kernel<<<dim3(SIMG_, H_), 128>>>(qkv_img, STXT_, nq, nk, rcos, rsin, Q, K, V);

    // ---- attention ----
    cudaFuncSetAttribute(attn_kernel, cudaFuncAttributeMaxDynamicSharedMemorySize,
                         ATTN_SMEM_BYTES);
    attn_kernel<<<dim3(SALL_ / 64, H_), 256, ATTN_SMEM_BYTES>>>(Q, K, V, attn);

    // ---- output projections ----
    const float* attn_txt = attn;
    const float* attn_img = attn + (size_t)STXT_ * INNER_;

    split_launch(attn_img, Aih, Ail, (long long)SIMG_ * INNER_);
    split_launch(attn_txt, Ath, Atl, (long long)STXT_ * INNER_);

    down_proj_kernel<<<SIMG_, 256>>>(attn_img, out_down, lr_a, INNER_);
    gemm_mma_kernel<<<dim3(D_ / 128, SIMG_ / 128), 256>>>(
        Aih, Ail, Boh, Bol, out_b, out_img, SIMG_, D_, INNER_);
    {
        long long tot = (long long)SIMG_ * (D_ / 4);
        rank_update_kernel<<<(unsigned)((tot + 255) / 256), 256>>>(
            lr_a, out_up, out_img, SIMG_, D_);
    }
    down_proj_kernel<<<STXT_, 256>>>(attn_txt, aout_down, lr_b, INNER_);
    gemm_mma_kernel<<<dim3(D_ / 128, STXT_ / 128), 256>>>(
        Ath, Atl, Baoh, Baol, aout_b, out_txt, STXT_, D_, INNER_);
    {
        long long tot = (long long)STXT_ * (D_ / 4);
        rank_update_kernel<<<(unsigned)((tot + 255) / 256), 256>>>(
            lr_b, aout_up, out_txt, STXT_, D_);
    }
}

// round 8
// speedup vs baseline: 2.5309x; 1.6001x over previous
#include <cuda_runtime.h>
#include <cuda_bf16.h>
#include <math.h>
#include <stdint.h>

#define D_      3072
#define H_      24
#define HD_     128
#define R_      32
#define INNER_  3072
#define QKV3_   9216
#define SIMG_   1536
#define STXT_   512
#define SALL_   2048

// scale(1/sqrt(128)) * log2(e)
#define SCALE2E_ 0.12751743f

// ---------------- scratch (device globals; no runtime allocation) ----------
static __device__ float g_qkv_img[SIMG_ * QKV3_];
static __device__ float g_qkv_txt[STXT_ * QKV3_];
static __device__ float g_lr_a[SIMG_ * R_];
static __device__ float g_lr_b[STXT_ * R_];
static __device__ float g_attn[SALL_ * INNER_];

// attention operands, bf16 hi/lo, layout [H][SALL][HD]
static __device__ __nv_bfloat16 g_qh[H_ * SALL_ * HD_], g_ql[H_ * SALL_ * HD_];
static __device__ __nv_bfloat16 g_kh[H_ * SALL_ * HD_], g_kl[H_ * SALL_ * HD_];
static __device__ __nv_bfloat16 g_vh[H_ * SALL_ * HD_], g_vl[H_ * SALL_ * HD_];

// bf16 hi/lo split buffers for projection GEMMs
static __device__ __nv_bfloat16 g_Aih[SIMG_ * D_],  g_Ail[SIMG_ * D_];
static __device__ __nv_bfloat16 g_Ath[STXT_ * D_],  g_Atl[STXT_ * D_];
static __device__ __nv_bfloat16 g_Bqh[QKV3_ * D_],  g_Bql[QKV3_ * D_];
static __device__ __nv_bfloat16 g_Baqh[QKV3_ * D_], g_Baql[QKV3_ * D_];
static __device__ __nv_bfloat16 g_Boh[D_ * INNER_], g_Bol[D_ * INNER_];
static __device__ __nv_bfloat16 g_Baoh[D_ * INNER_], g_Baol[D_ * INNER_];

// ---------------------------------------------------------------------------
// fp32 -> bf16 hi/lo split (elementwise), n multiple of 4
// ---------------------------------------------------------------------------
__global__ void __launch_bounds__(256) split_bf16_kernel(
    const float* __restrict__ X, __nv_bfloat16* __restrict__ Xh,
    __nv_bfloat16* __restrict__ Xl, int n4)
{
    int i = blockIdx.x * blockDim.x + threadIdx.x;
    if (i >= n4) return;
    float4 v = ((const float4*)X)[i];
    union { __nv_bfloat16 b[4]; uint2 u; } ph, pl;
    ph.b[0] = __float2bfloat16(v.x);
    ph.b[1] = __float2bfloat16(v.y);
    ph.b[2] = __float2bfloat16(v.z);
    ph.b[3] = __float2bfloat16(v.w);
    pl.b[0] = __float2bfloat16(v.x - __bfloat162float(ph.b[0]));
    pl.b[1] = __float2bfloat16(v.y - __bfloat162float(ph.b[1]));
    pl.b[2] = __float2bfloat16(v.z - __bfloat162float(ph.b[2]));
    pl.b[3] = __float2bfloat16(v.w - __bfloat162float(ph.b[3]));
    ((uint2*)Xh)[i] = ph.u;
    ((uint2*)Xl)[i] = pl.u;
}

// ---------------------------------------------------------------------------
// mma helpers
// ---------------------------------------------------------------------------
__device__ __forceinline__ uint32_t sptr(const void* p) {
    return (uint32_t)__cvta_generic_to_shared(p);
}
__device__ __forceinline__ void ldsm_x4(uint32_t* r, uint32_t a) {
    asm volatile("ldmatrix.sync.aligned.m8n8.x4.shared.b16 {%0,%1,%2,%3}, [%4];"
                 : "=r"(r[0]), "=r"(r[1]), "=r"(r[2]), "=r"(r[3]) : "r"(a));
}
__device__ __forceinline__ void ldsm_x4_t(uint32_t* r, uint32_t a) {
    asm volatile("ldmatrix.sync.aligned.m8n8.x4.trans.shared.b16 {%0,%1,%2,%3}, [%4];"
                 : "=r"(r[0]), "=r"(r[1]), "=r"(r[2]), "=r"(r[3]) : "r"(a));
}
__device__ __forceinline__ void mma_bf16(float* c, const uint32_t* a,
                                         uint32_t b0, uint32_t b1) {
    asm volatile(
        "mma.sync.aligned.m16n8k16.row.col.f32.bf16.bf16.f32 "
        "{%0,%1,%2,%3},{%4,%5,%6,%7},{%8,%9},{%0,%1,%2,%3};"
        : "+f"(c[0]), "+f"(c[1]), "+f"(c[2]), "+f"(c[3])
        : "r"(a[0]), "r"(a[1]), "r"(a[2]), "r"(a[3]), "r"(b0), "r"(b1));
}
__device__ __forceinline__ uint32_t packbf(float lo, float hi) {
    uint32_t r;
    asm("cvt.rn.bf16x2.f32 %0, %1, %2;" : "=r"(r) : "f"(hi), "f"(lo));
    return r;
}
__device__ __forceinline__ float lobf(uint32_t r) { return __uint_as_float(r << 16); }
__device__ __forceinline__ float hibf(uint32_t r) { return __uint_as_float(r & 0xffff0000u); }

// ---------------------------------------------------------------------------
// C[M,N] = A[M,K] @ B[N,K]^T (+bias), bf16 hi/lo 3-product GEMM (unchanged).
// ---------------------------------------------------------------------------
#define LDA_ 40

__global__ void __launch_bounds__(256) gemm_mma_kernel(
    const __nv_bfloat16* __restrict__ Ah, const __nv_bfloat16* __restrict__ Al,
    const __nv_bfloat16* __restrict__ Bh, const __nv_bfloat16* __restrict__ Bl,
    const float* __restrict__ bias, float* __restrict__ C,
    int M, int N, int K)
{
    __shared__ __nv_bfloat16 sAh[128 * LDA_], sAl[128 * LDA_];
    __shared__ __nv_bfloat16 sBh[128 * LDA_], sBl[128 * LDA_];

    const int tid  = threadIdx.x;
    const int brow = blockIdx.y * 128;
    const int bcol = blockIdx.x * 128;
    const int warp = tid >> 5, lane = tid & 31;
    const int wm = (warp & 1) * 64;
    const int wn = (warp >> 1) * 32;

    const int lrow = tid >> 2;
    const int lseg = (tid & 3) * 8;
    const __nv_bfloat16* pAh0 = Ah + (size_t)(brow + lrow) * K + lseg;
    const __nv_bfloat16* pAh1 = Ah + (size_t)(brow + lrow + 64) * K + lseg;
    const __nv_bfloat16* pAl0 = Al + (size_t)(brow + lrow) * K + lseg;
    const __nv_bfloat16* pAl1 = Al + (size_t)(brow + lrow + 64) * K + lseg;
    const __nv_bfloat16* pBh0 = Bh + (size_t)(bcol + lrow) * K + lseg;
    const __nv_bfloat16* pBh1 = Bh + (size_t)(bcol + lrow + 64) * K + lseg;
    const __nv_bfloat16* pBl0 = Bl + (size_t)(bcol + lrow) * K + lseg;
    const __nv_bfloat16* pBl1 = Bl + (size_t)(bcol + lrow + 64) * K + lseg;

    float acc[4][4][4];
#pragma unroll
    for (int i = 0; i < 4; i++)
#pragma unroll
        for (int j = 0; j < 4; j++)
#pragma unroll
            for (int e = 0; e < 4; e++) acc[i][j][e] = 0.f;

    const int qa = lane >> 3, ra = lane & 7;
    const int a_row = (qa & 1) * 8 + ra;
    const int a_col = (qa >> 1) * 8;
    const int b_row = (qa >> 1) * 8 + ra;
    const int b_col = (qa & 1) * 8;

    for (int kt = 0; kt < K; kt += 32) {
        uint4 vah0 = *(const uint4*)(pAh0 + kt);
        uint4 vah1 = *(const uint4*)(pAh1 + kt);
        uint4 val0 = *(const uint4*)(pAl0 + kt);
        uint4 val1 = *(const uint4*)(pAl1 + kt);
        uint4 vbh0 = *(const uint4*)(pBh0 + kt);
        uint4 vbh1 = *(const uint4*)(pBh1 + kt);
        uint4 vbl0 = *(const uint4*)(pBl0 + kt);
        uint4 vbl1 = *(const uint4*)(pBl1 + kt);
        __syncthreads();
        *(uint4*)&sAh[lrow * LDA_ + lseg]        = vah0;
        *(uint4*)&sAh[(lrow + 64) * LDA_ + lseg] = vah1;
        *(uint4*)&sAl[lrow * LDA_ + lseg]        = val0;
        *(uint4*)&sAl[(lrow + 64) * LDA_ + lseg] = val1;
        *(uint4*)&sBh[lrow * LDA_ + lseg]        = vbh0;
        *(uint4*)&sBh[(lrow + 64) * LDA_ + lseg] = vbh1;
        *(uint4*)&sBl[lrow * LDA_ + lseg]        = vbl0;
        *(uint4*)&sBl[(lrow + 64) * LDA_ + lseg] = vbl1;
        __syncthreads();

#pragma unroll
        for (int kb = 0; kb < 32; kb += 16) {
            uint32_t ah[4][4], al[4][4], bh[2][4], bl[2][4];
#pragma unroll
            for (int mf = 0; mf < 4; mf++) {
                int r = wm + mf * 16 + a_row;
                ldsm_x4(ah[mf], sptr(&sAh[r * LDA_ + kb + a_col]));
                ldsm_x4(al[mf], sptr(&sAl[r * LDA_ + kb + a_col]));
            }
#pragma unroll
            for (int p = 0; p < 2; p++) {
                int r = wn + p * 16 + b_row;
                ldsm_x4(bh[p], sptr(&sBh[r * LDA_ + kb + b_col]));
                ldsm_x4(bl[p], sptr(&sBl[r * LDA_ + kb + b_col]));
            }
#pragma unroll
            for (int mf = 0; mf < 4; mf++)
#pragma unroll
                for (int nf = 0; nf < 4; nf++) {
                    const int p = nf >> 1, o = (nf & 1) * 2;
                    mma_bf16(acc[mf][nf], ah[mf], bh[p][o], bh[p][o + 1]);
                    mma_bf16(acc[mf][nf], ah[mf], bl[p][o], bl[p][o + 1]);
                    mma_bf16(acc[mf][nf], al[mf], bh[p][o], bh[p][o + 1]);
                }
        }
    }

    const int g = lane >> 2, t = lane & 3;
#pragma unroll
    for (int mf = 0; mf < 4; mf++) {
        int r0 = brow + wm + mf * 16 + g;
#pragma unroll
        for (int nf = 0; nf < 4; nf++) {
            int col = bcol + wn + nf * 8 + t * 2;
            float b0 = 0.f, b1 = 0.f;
            if (bias) { b0 = bias[col]; b1 = bias[col + 1]; }
            float2 v0, v1;
            v0.x = acc[mf][nf][0] + b0; v0.y = acc[mf][nf][1] + b1;
            v1.x = acc[mf][nf][2] + b0; v1.y = acc[mf][nf][3] + b1;
            *(float2*)(C + (size_t)r0 * N + col)       = v0;
            *(float2*)(C + (size_t)(r0 + 8) * N + col) = v1;
        }
    }
}

// ---------------------------------------------------------------------------
// C[M,R] = A[M,K] @ B[K,R] ; R = 32.
// ---------------------------------------------------------------------------
__global__ void __launch_bounds__(256) down_proj_kernel(
    const float* __restrict__ A, const float* __restrict__ B,
    float* __restrict__ C, int K)
{
    const int m = blockIdx.x;
    const int c = threadIdx.x & 31;
    const int kc = threadIdx.x >> 5;
    const float* a = A + (size_t)m * K;
    const int kchunk = K >> 3;
    const int k0 = kc * kchunk;
    float s = 0.f;
    for (int k = k0; k < k0 + kchunk; k++)
        s += a[k] * B[k * R_ + c];
    __shared__ float red[256];
    red[threadIdx.x] = s;
    __syncthreads();
    if (kc == 0) {
        float t = s;
#pragma unroll
        for (int i = 1; i < 8; i++) t += red[i * 32 + c];
        C[m * R_ + c] = t;
    }
}

// ---------------------------------------------------------------------------
// C[M,N] += T[M,32] @ U[32,N]
// ---------------------------------------------------------------------------
__global__ void __launch_bounds__(256) rank_update_kernel(
    const float* __restrict__ T, const float* __restrict__ U,
    float* __restrict__ C, int M, int N)
{
    const int n4cnt = N >> 2;
    long long idx = (long long)blockIdx.x * blockDim.x + threadIdx.x;
    if (idx >= (long long)M * n4cnt) return;
    int m = (int)(idx / n4cnt);
    int n4 = (int)(idx % n4cnt);
    float4 c = ((float4*)C)[(size_t)m * n4cnt + n4];
    const float* t = T + (size_t)m * R_;
#pragma unroll
    for (int k = 0; k < R_; k++) {
        float tv = t[k];
        float4 u = ((const float4*)(U + (size_t)k * N))[n4];
        c.x += tv * u.x; c.y += tv * u.y; c.z += tv * u.z; c.w += tv * u.w;
    }
    ((float4*)C)[(size_t)m * n4cnt + n4] = c;
}

// ---------------------------------------------------------------------------
// QKV post: heads, RMSNorm, RoPE; writes bf16 hi/lo Q(scaled)/K/V to [H][S][HD]
// ---------------------------------------------------------------------------
__global__ void __launch_bounds__(128) qkv_post_kernel(
    const float* __restrict__ qkv, int pos_off,
    const float* __restrict__ wq, const float* __restrict__ wk,
    const float* __restrict__ rcos, const float* __restrict__ rsin,
    __nv_bfloat16* __restrict__ qh, __nv_bfloat16* __restrict__ ql,
    __nv_bfloat16* __restrict__ kh, __nv_bfloat16* __restrict__ kl,
    __nv_bfloat16* __restrict__ vh, __nv_bfloat16* __restrict__ vl)
{
    const int s = blockIdx.x;
    const int h = blockIdx.y;
    const int d = threadIdx.x;
    const float* row = qkv + (size_t)s * QKV3_ + h * HD_;
    float q = row[d];
    float k = row[INNER_ + d];
    float v = row[2 * INNER_ + d];

    __shared__ float sh[8];
    float sq = q * q, sk = k * k;
#pragma unroll
    for (int o = 16; o > 0; o >>= 1) {
        sq += __shfl_xor_sync(0xffffffffu, sq, o);
        sk += __shfl_xor_sync(0xffffffffu, sk, o);
    }
    int w = d >> 5;
    if ((d & 31) == 0) { sh[w] = sq; sh[4 + w] = sk; }
    __syncthreads();
    sq = sh[0] + sh[1] + sh[2] + sh[3];
    sk = sh[4] + sh[5] + sh[6] + sh[7];
    float rq = rsqrtf(sq * (1.f / HD_) + 1e-5f);
    float rk = rsqrtf(sk * (1.f / HD_) + 1e-5f);
    q = q * rq * wq[d];
    k = k * rk * wk[d];

    const int pos = pos_off + s;
    float c = rcos[pos * 64 + (d >> 1)];
    float sn = rsin[pos * 64 + (d >> 1)];
    float qo = __shfl_xor_sync(0xffffffffu, q, 1);
    float ko = __shfl_xor_sync(0xffffffffu, k, 1);
    float qr = (d & 1) ? (qo * sn + q * c) : (q * c - qo * sn);
    float kr = (d & 1) ? (ko * sn + k * c) : (k * c - ko * sn);

    qr *= SCALE2E_;   // fold softmax scale * log2(e) into Q

    size_t o = ((size_t)h * SALL_ + pos) * HD_ + d;
    __nv_bfloat16 hq = __float2bfloat16(qr);
    __nv_bfloat16 hk = __float2bfloat16(kr);
    __nv_bfloat16 hv = __float2bfloat16(v);
    qh[o] = hq; ql[o] = __float2bfloat16(qr - __bfloat162float(hq));
    kh[o] = hk; kl[o] = __float2bfloat16(kr - __bfloat162float(hk));
    vh[o] = hv; vl[o] = __float2bfloat16(v  - __bfloat162float(hv));
}

// ---------------------------------------------------------------------------
// Tensor-core flash attention. BM=128 (8 warps x 16 rows), BKV=64.
// QK^T: 3-product bf16 hi/lo. Softmax base-2, warp-local. PV: P packed from
// S-fragments in registers (hi/lo), V hi/lo via ldmatrix.trans, 3 products.
// ---------------------------------------------------------------------------
#define ALDA_ 136
#define ATTN_SMEM_ ((2 * 128 + 4 * 64) * ALDA_ * 2)

__global__ void __launch_bounds__(256, 1) attn_mma_kernel(
    const __nv_bfloat16* __restrict__ Qh, const __nv_bfloat16* __restrict__ Ql,
    const __nv_bfloat16* __restrict__ Kh, const __nv_bfloat16* __restrict__ Kl,
    const __nv_bfloat16* __restrict__ Vh, const __nv_bfloat16* __restrict__ Vl,
    float* __restrict__ O)
{
    extern __shared__ __nv_bfloat16 sb[];
    __nv_bfloat16* sQh = sb;
    __nv_bfloat16* sQl = sQh + 128 * ALDA_;
    __nv_bfloat16* sKh = sQl + 128 * ALDA_;
    __nv_bfloat16* sKl = sKh + 64 * ALDA_;
    __nv_bfloat16* sVh = sKl + 64 * ALDA_;
    __nv_bfloat16* sVl = sVh + 64 * ALDA_;

    const int head = blockIdx.y;
    const int q0 = blockIdx.x * 128;
    const int tid = threadIdx.x;
    const int warp = tid >> 5, lane = tid & 31;
    const size_t hbase = (size_t)head * SALL_ * HD_;

    // load Q tile (128 x 128 halves): 2048 uint4 per array
    {
        const uint4* gqh = (const uint4*)(Qh + hbase + (size_t)q0 * HD_);
        const uint4* gql = (const uint4*)(Ql + hbase + (size_t)q0 * HD_);
#pragma unroll
        for (int k = 0; k < 8; k++) {
            int i = tid + k * 256;
            int row = i >> 4, seg = i & 15;
            *(uint4*)&sQh[row * ALDA_ + seg * 8] = gqh[i];
            *(uint4*)&sQl[row * ALDA_ + seg * 8] = gql[i];
        }
    }

    float accO[16][4];
#pragma unroll
    for (int i = 0; i < 16; i++)
#pragma unroll
        for (int e = 0; e < 4; e++) accO[i][e] = 0.f;
    float m0 = -1e30f, m1 = -1e30f, l0 = 0.f, l1 = 0.f;

    const int qa = lane >> 3, ra = lane & 7;
    const int arow = warp * 16 + (qa & 1) * 8 + ra;
    const int acol = (qa >> 1) * 8;
    const int vrow = lane & 15;
    const int vcol = (lane >> 4) * 8;

    for (int kt = 0; kt < SALL_ / 64; kt++) {
        __syncthreads();
        {
            const size_t kvoff = hbase + (size_t)(kt * 64) * HD_;
            const uint4* gkh = (const uint4*)(Kh + kvoff);
            const uint4* gkl = (const uint4*)(Kl + kvoff);
            const uint4* gvh = (const uint4*)(Vh + kvoff);
            const uint4* gvl = (const uint4*)(Vl + kvoff);
#pragma unroll
            for (int k = 0; k < 4; k++) {
                int i = tid + k * 256;
                int row = i >> 4, seg = i & 15;
                int dst = row * ALDA_ + seg * 8;
                *(uint4*)&sKh[dst] = gkh[i];
                *(uint4*)&sKl[dst] = gkl[i];
                *(uint4*)&sVh[dst] = gvh[i];
                *(uint4*)&sVl[dst] = gvl[i];
            }
        }
        __syncthreads();

        // ---- S = Q K^T  (16 rows x 64 cols per warp) ----
        float accS[8][4];
#pragma unroll
        for (int j = 0; j < 8; j++)
#pragma unroll
            for (int e = 0; e < 4; e++) accS[j][e] = 0.f;

#pragma unroll
        for (int kc = 0; kc < 8; kc++) {
            uint32_t ah[4], al[4];
            ldsm_x4(ah, sptr(&sQh[arow * ALDA_ + kc * 16 + acol]));
            ldsm_x4(al, sptr(&sQl[arow * ALDA_ + kc * 16 + acol]));
#pragma unroll
            for (int np = 0; np < 4; np++) {
                uint32_t bh[4], bl[4];
                int br = np * 16 + (qa & 1) * 8 + ra;
                ldsm_x4(bh, sptr(&sKh[br * ALDA_ + kc * 16 + acol]));
                ldsm_x4(bl, sptr(&sKl[br * ALDA_ + kc * 16 + acol]));
                mma_bf16(accS[2 * np],     ah, bh[0], bh[2]);
                mma_bf16(accS[2 * np],     ah, bl[0], bl[2]);
                mma_bf16(accS[2 * np],     al, bh[0], bh[2]);
                mma_bf16(accS[2 * np + 1], ah, bh[1], bh[3]);
                mma_bf16(accS[2 * np + 1], ah, bl[1], bl[3]);
                mma_bf16(accS[2 * np + 1], al, bh[1], bh[3]);
            }
        }

        // ---- online softmax (base 2; scale folded into Q) ----
        float ml0 = -1e30f, ml1 = -1e30f;
#pragma unroll
        for (int j = 0; j < 8; j++) {
            ml0 = fmaxf(ml0, fmaxf(accS[j][0], accS[j][1]));
            ml1 = fmaxf(ml1, fmaxf(accS[j][2], accS[j][3]));
        }
#pragma unroll
        for (int o = 1; o < 4; o <<= 1) {
            ml0 = fmaxf(ml0, __shfl_xor_sync(0xffffffffu, ml0, o));
            ml1 = fmaxf(ml1, __shfl_xor_sync(0xffffffffu, ml1, o));
        }
        float mn0 = fmaxf(m0, ml0), mn1 = fmaxf(m1, ml1);
        float f0 = exp2f(m0 - mn0), f1 = exp2f(m1 - mn1);
        float s0 = 0.f, s1 = 0.f;
#pragma unroll
        for (int j = 0; j < 8; j++) {
            accS[j][0] = exp2f(accS[j][0] - mn0);
            accS[j][1] = exp2f(accS[j][1] - mn0);
            accS[j][2] = exp2f(accS[j][2] - mn1);
            accS[j][3] = exp2f(accS[j][3] - mn1);
            s0 += accS[j][0] + accS[j][1];
            s1 += accS[j][2] + accS[j][3];
        }
#pragma unroll
        for (int o = 1; o < 4; o <<= 1) {
            s0 += __shfl_xor_sync(0xffffffffu, s0, o);
            s1 += __shfl_xor_sync(0xffffffffu, s1, o);
        }
        l0 = l0 * f0 + s0; l1 = l1 * f1 + s1;
        m0 = mn0; m1 = mn1;
#pragma unroll
        for (int i = 0; i < 16; i++) {
            accO[i][0] *= f0; accO[i][1] *= f0;
            accO[i][2] *= f1; accO[i][3] *= f1;
        }

        // ---- O += P V ----
#pragma unroll
        for (int kc2 = 0; kc2 < 4; kc2++) {
            const int j0 = 2 * kc2, j1 = j0 + 1;
            uint32_t pah[4], pal[4];
            pah[0] = packbf(accS[j0][0], accS[j0][1]);
            pah[1] = packbf(accS[j0][2], accS[j0][3]);
            pah[2] = packbf(accS[j1][0], accS[j1][1]);
            pah[3] = packbf(accS[j1][2], accS[j1][3]);
            pal[0] = packbf(accS[j0][0] - lobf(pah[0]), accS[j0][1] - hibf(pah[0]));
            pal[1] = packbf(accS[j0][2] - lobf(pah[1]), accS[j0][3] - hibf(pah[1]));
            pal[2] = packbf(accS[j1][0] - lobf(pah[2]), accS[j1][1] - hibf(pah[2]));
            pal[3] = packbf(accS[j1][2] - lobf(pah[3]), accS[j1][3] - hibf(pah[3]));

            const int vr = kc2 * 16 + vrow;
#pragma unroll
            for (int np = 0; np < 8; np++) {
                uint32_t vbh[4], vbl[4];
                ldsm_x4_t(vbh, sptr(&sVh[vr * ALDA_ + np * 16 + vcol]));
                ldsm_x4_t(vbl, sptr(&sVl[vr * ALDA_ + np * 16 + vcol]));
                mma_bf16(accO[2 * np],     pah, vbh[0], vbh[1]);
                mma_bf16(accO[2 * np],     pah, vbl[0], vbl[1]);
                mma_bf16(accO[2 * np],     pal, vbh[0], vbh[1]);
                mma_bf16(accO[2 * np + 1], pah, vbh[2], vbh[3]);
                mma_bf16(accO[2 * np + 1], pah, vbl[2], vbl[3]);
                mma_bf16(accO[2 * np + 1], pal, vbh[2], vbh[3]);
            }
        }
    }

    // ---- epilogue: normalize, write [S][INNER] fp32 ----
    const float inv0 = 1.f / l0, inv1 = 1.f / l1;
    const int r0 = q0 + warp * 16 + (lane >> 2);
    const int cb = head * HD_ + (lane & 3) * 2;
#pragma unroll
    for (int nt = 0; nt < 16; nt++) {
        float2 v0, v1;
        v0.x = accO[nt][0] * inv0; v0.y = accO[nt][1] * inv0;
        v1.x = accO[nt][2] * inv1; v1.y = accO[nt][3] * inv1;
        *(float2*)&O[(size_t)r0 * INNER_ + cb + nt * 8] = v0;
        *(float2*)&O[(size_t)(r0 + 8) * INNER_ + cb + nt * 8] = v1;
    }
}

// ---------------------------------------------------------------------------
static inline void split_launch(const float* X, __nv_bfloat16* h, __nv_bfloat16* l,
                                long long n)
{
    int n4 = (int)(n >> 2);
    split_bf16_kernel<<<(n4 + 255) / 256, 256>>>(X, h, l, n4);
}

extern "C" void kernel_launch(void* const* d_in, const int* in_sizes, int n_in,
                              void* d_out, int out_size)
{
    const float* hs        = (const float*)d_in[0];
    const float* ehs       = (const float*)d_in[1];
    const float* rcos      = (const float*)d_in[2];
    const float* rsin      = (const float*)d_in[3];
    const float* qkv_w     = (const float*)d_in[4];
    const float* qkv_down  = (const float*)d_in[5];
    const float* qkv_up    = (const float*)d_in[6];
    const float* aqkv_w    = (const float*)d_in[7];
    const float* aqkv_down = (const float*)d_in[8];
    const float* aqkv_up   = (const float*)d_in[9];
    const float* out_w     = (const float*)d_in[10];
    const float* out_down  = (const float*)d_in[11];
    const float* out_up    = (const float*)d_in[12];
    const float* out_b     = (const float*)d_in[13];
    const float* aout_w    = (const float*)d_in[14];
    const float* aout_down = (const float*)d_in[15];
    const float* aout_up   = (const float*)d_in[16];
    const float* aout_b    = (const float*)d_in[17];
    const float* nq        = (const float*)d_in[18];
    const float* nk        = (const float*)d_in[19];
    const float* naq       = (const float*)d_in[20];
    const float* nak       = (const float*)d_in[21];

    float *qkv_img, *qkv_txt, *lr_a, *lr_b, *attn;
    cudaGetSymbolAddress((void**)&qkv_img, g_qkv_img);
    cudaGetSymbolAddress((void**)&qkv_txt, g_qkv_txt);
    cudaGetSymbolAddress((void**)&lr_a, g_lr_a);
    cudaGetSymbolAddress((void**)&lr_b, g_lr_b);
    cudaGetSymbolAddress((void**)&attn, g_attn);

    __nv_bfloat16 *qbh, *qbl, *kbh, *kbl, *vbh, *vbl;
    cudaGetSymbolAddress((void**)&qbh, g_qh);
    cudaGetSymbolAddress((void**)&qbl, g_ql);
    cudaGetSymbolAddress((void**)&kbh, g_kh);
    cudaGetSymbolAddress((void**)&kbl, g_kl);
    cudaGetSymbolAddress((void**)&vbh, g_vh);
    cudaGetSymbolAddress((void**)&vbl, g_vl);

    __nv_bfloat16 *Aih, *Ail, *Ath, *Atl;
    __nv_bfloat16 *Bqh, *Bql, *Baqh, *Baql, *Boh, *Bol, *Baoh, *Baol;
    cudaGetSymbolAddress((void**)&Aih, g_Aih);
    cudaGetSymbolAddress((void**)&Ail, g_Ail);
    cudaGetSymbolAddress((void**)&Ath, g_Ath);
    cudaGetSymbolAddress((void**)&Atl, g_Atl);
    cudaGetSymbolAddress((void**)&Bqh, g_Bqh);
    cudaGetSymbolAddress((void**)&Bql, g_Bql);
    cudaGetSymbolAddress((void**)&Baqh, g_Baqh);
    cudaGetSymbolAddress((void**)&Baql, g_Baql);
    cudaGetSymbolAddress((void**)&Boh, g_Boh);
    cudaGetSymbolAddress((void**)&Bol, g_Bol);
    cudaGetSymbolAddress((void**)&Baoh, g_Baoh);
    cudaGetSymbolAddress((void**)&Baol, g_Baol);

    float* out_img = (float*)d_out;
    float* out_txt = (float*)d_out + (size_t)SIMG_ * D_;

    // ---- bf16 hi/lo conversions ----
    split_launch(hs,     Aih,  Ail,  (long long)SIMG_ * D_);
    split_launch(ehs,    Ath,  Atl,  (long long)STXT_ * D_);
    split_launch(qkv_w,  Bqh,  Bql,  (long long)QKV3_ * D_);
    split_launch(aqkv_w, Baqh, Baql, (long long)QKV3_ * D_);
    split_launch(out_w,  Boh,  Bol,  (long long)D_ * INNER_);
    split_launch(aout_w, Baoh, Baol, (long long)D_ * INNER_);

    // ---- QKV projections ----
    down_proj_kernel<<<SIMG_, 256>>>(hs, qkv_down, lr_a, D_);
    gemm_mma_kernel<<<dim3(QKV3_ / 128, SIMG_ / 128), 256>>>(
        Aih, Ail, Bqh, Bql, nullptr, qkv_img, SIMG_, QKV3_, D_);
    {
        long long tot = (long long)SIMG_ * (QKV3_ / 4);
        rank_update_kernel<<<(unsigned)((tot + 255) / 256), 256>>>(
            lr_a, qkv_up, qkv_img, SIMG_, QKV3_);
    }
    down_proj_kernel<<<STXT_, 256>>>(ehs, aqkv_down, lr_b, D_);
    gemm_mma_kernel<<<dim3(QKV3_ / 128, STXT_ / 128), 256>>>(
        Ath, Atl, Baqh, Baql, nullptr, qkv_txt, STXT_, QKV3_, D_);
    {
        long long tot = (long long)STXT_ * (QKV3_ / 4);
        rank_update_kernel<<<(unsigned)((tot + 255) / 256), 256>>>(
            lr_b, aqkv_up, qkv_txt, STXT_, QKV3_);
    }

    // ---- heads + RMSNorm + RoPE -> bf16 hi/lo Q/K/V (txt first, then img) ----
    qkv_post_kernel<<<dim3(STXT_, H_), 128>>>(qkv_txt, 0, naq, nak, rcos, rsin,
                                              qbh, qbl, kbh, kbl, vbh, vbl);
    qkv_post_kernel<<<dim3(SIMG_, H_), 128>>>(qkv_img, STXT_, nq, nk, rcos, rsin,
                                              qbh, qbl, kbh, kbl, vbh, vbl);

    // ---- tensor-core attention ----
    cudaFuncSetAttribute(attn_mma_kernel, cudaFuncAttributeMaxDynamicSharedMemorySize,
                         ATTN_SMEM_);
    attn_mma_kernel<<<dim3(SALL_ / 128, H_), 256, ATTN_SMEM_>>>(
        qbh, qbl, kbh, kbl, vbh, vbl, attn);

    // ---- output projections ----
    const float* attn_txt = attn;
    const float* attn_img = attn + (size_t)STXT_ * INNER_;

    split_launch(attn_img, Aih, Ail, (long long)SIMG_ * INNER_);
    split_launch(attn_txt, Ath, Atl, (long long)STXT_ * INNER_);

    down_proj_kernel<<<SIMG_, 256>>>(attn_img, out_down, lr_a, INNER_);
    gemm_mma_kernel<<<dim3(D_ / 128, SIMG_ / 128), 256>>>(
        Aih, Ail, Boh, Bol, out_b, out_img, SIMG_, D_, INNER_);
    {
        long long tot = (long long)SIMG_ * (D_ / 4);
        rank_update_kernel<<<(unsigned)((tot + 255) / 256), 256>>>(
            lr_a, out_up, out_img, SIMG_, D_);
    }
    down_proj_kernel<<<STXT_, 256>>>(attn_txt, aout_down, lr_b, INNER_);
    gemm_mma_kernel<<<dim3(D_ / 128, STXT_ / 128), 256>>>(
        Ath, Atl, Baoh, Baol, aout_b, out_txt, STXT_, D_, INNER_);
    {
        long long tot = (long long)STXT_ * (D_ / 4);
        rank_update_kernel<<<(unsigned)((tot + 255) / 256), 256>>>(
            lr_b, aout_up, out_txt, STXT_, D_);
    }
}